// round 4
// baseline (speedup 1.0000x reference)
#include <cuda_runtime.h>
#include <math.h>

#define Bn 2
#define C 32
#define H 256
#define W 512
#define LH 64
#define LW 128

// dynamic shared layout (floats)
#define OFF_W0LR 0          // 32*32
#define OFF_W0HR 1024       // 32*32
#define OFF_W1   2048       // 32*16
#define OFF_W2   2560       // 16*8
#define OFF_W3   2688       // 8  (+8 pad)
#define OFF_DT   2704       // 9*16*36 = 5184
#define OFF_P    7888       // 3*18*36 = 1944
#define OFF_H    9832       // 256*36  = 9216
#define SMEM_FLOATS (9832 + 9216)   // 19048 floats = 76192 bytes

// ---------------------------------------------------------------------------
// Single fused kernel. Tile = 64 wide x 4 tall, 256 threads, 1 pixel/thread.
// hpart lives in SHARED (sH) so the 9-direction loop has tiny register
// liveness (no spills).
// ---------------------------------------------------------------------------
__global__ __launch_bounds__(256, 2) void k_fused(
    const float* __restrict__ lr,
    const float* __restrict__ hr,
    const float* __restrict__ w0,
    const float* __restrict__ w1,
    const float* __restrict__ w2,
    const float* __restrict__ w3,
    float* __restrict__ out)
{
    extern __shared__ float smem[];
    float* sW0lr = smem + OFF_W0LR;   // [c][o]
    float* sW0hr = smem + OFF_W0HR;   // [c][o]
    float* sW1   = smem + OFF_W1;     // [c][o]
    float* sW2   = smem + OFF_W2;     // [c][o]
    float* sW3   = smem + OFF_W3;
    float* sDT   = smem + OFF_DT;     // [k*16+phase][36]
    float* sP    = smem + OFF_P;      // [ly*18+lx][36]
    float* sH    = smem + OFF_H;      // [tid][36]

    const int tid = threadIdx.x;
    const int x0  = blockIdx.x * 64;
    const int y0  = blockIdx.y * 4;
    const int b   = blockIdx.z;
    const int lx0 = x0 >> 2;

    // ---- stage weights ----
    for (int i = tid; i < 32 * 32; i += 256) {
        int c = i >> 5, o = i & 31;
        sW0lr[i] = w0[o * 66 + c];
        sW0hr[i] = w0[o * 66 + 32 + c];
    }
    for (int i = tid; i < 32 * 16; i += 256) {
        int c = i >> 4, o = i & 15;
        sW1[i] = w1[o * 32 + c];
    }
    for (int i = tid; i < 16 * 8; i += 256) {
        int c = i >> 3, o = i & 7;
        sW2[i] = w2[o * 16 + c];
    }
    if (tid < 8) sW3[tid] = w3[tid];

    // ---- dt table: W0_d @ d_k(py,px) ----
    for (int i = tid; i < 9 * 16 * 32; i += 256) {
        int o  = i & 31;
        int px = (i >> 5) & 3;
        int py = (i >> 7) & 3;
        int k  = i >> 9;
        const float base[4] = {-2.f, -1.f, 1.f, 2.f};
        float bx = base[px], by = base[py];
        float d0, d1;
        if (k == 0)                { d0 = bx;              d1 = by;              }
        else if (k == 1 || k == 5) { d0 = 4.f - (float)px; d1 = by;              }
        else if (k == 2 || k == 6) { d0 = (float)px + 1.f; d1 = by;              }
        else if (k == 3 || k == 7) { d0 = bx;              d1 = 4.f - (float)py; }
        else                       { d0 = bx;              d1 = (float)py + 1.f; }
        sDT[(k * 16 + py * 4 + px) * 36 + o] =
            w0[o * 66 + 64] * d0 + w0[o * 66 + 65] * d1;
    }
    __syncthreads();

    // ---- P halo: 54 lr pixels x 32 outputs, 4 threads per pixel ----
    if (tid < 216) {
        int pix = tid >> 2;            // 0..53
        int og  = (tid & 3) * 8;
        int lxl = pix % 18, lyl = pix / 18;
        int glx = min(max(lx0 - 1 + lxl, 0), LW - 1);
        int gly = min(max((y0 >> 2) - 1 + lyl, 0), LH - 1);
        const float* lp = lr + ((size_t)(b * C) * LH + gly) * LW + glx;
        float acc[8];
#pragma unroll
        for (int o = 0; o < 8; o++) acc[o] = 0.f;
#pragma unroll
        for (int c = 0; c < 32; c++) {
            float v = lp[(size_t)c * LH * LW];
#pragma unroll
            for (int o = 0; o < 8; o++)
                acc[o] = fmaf(v, sW0lr[c * 32 + og + o], acc[o]);
        }
        float* Pd = &sP[(lyl * 18 + lxl) * 36 + og];
#pragma unroll
        for (int o = 0; o < 8; o++) Pd[o] = acc[o];
    }

    // ---- hr-part of layer 0 (registers -> own shared row) ----
    const int x  = x0 + (tid & 63);
    const int y  = y0 + (tid >> 6);
    const int px = x & 3, py = y & 3;
    {
        const float* hp = hr + ((size_t)b * C * H + y) * W + x;
        float hpart[32];
#pragma unroll
        for (int o = 0; o < 32; o++) hpart[o] = 0.f;
#pragma unroll
        for (int c = 0; c < 32; c++) {
            float v = hp[(size_t)c * H * W];
#pragma unroll
            for (int o = 0; o < 32; o++)
                hpart[o] = fmaf(v, sW0hr[c * 32 + o], hpart[o]);
        }
        float* Hrow = &sH[tid * 36];
#pragma unroll
        for (int o = 0; o < 32; o += 4)
            *(float4*)&Hrow[o] = make_float4(hpart[o], hpart[o+1],
                                             hpart[o+2], hpart[o+3]);
    }
    __syncthreads();   // sP ready (sH row is own-thread, safe anyway)

    // direction offsets: dy=-1 for k in {3,5,6}, dy=+1 for {4,7,8};
    //                    dx=-1 for {1,5,7},     dx=+1 for {2,6,8}
    const unsigned NY = (1u<<3)|(1u<<5)|(1u<<6), PY = (1u<<4)|(1u<<7)|(1u<<8);
    const unsigned NX = (1u<<1)|(1u<<5)|(1u<<7), PX = (1u<<2)|(1u<<6)|(1u<<8);

    const int lxc = ((x >> 2) - lx0) + 1;
    const float4* Hp = (const float4*)&sH[tid * 36];

    float v9[9];

#pragma unroll 1
    for (int k = 0; k < 9; k++) {
        int dy = (int)((PY >> k) & 1u) - (int)((NY >> k) & 1u);
        int dx = (int)((PX >> k) & 1u) - (int)((NX >> k) & 1u);
        int xn = x + dx * 4, yn = y + dy * 4;
        bool valid = (xn >= 0) & (xn < W) & (yn >= 0) & (yn < H);

        const float4* Pn4 = (const float4*)&sP[((1 + dy) * 18 + lxc + dx) * 36];
        const float4* dt4 = (const float4*)&sDT[(k * 16 + py * 4 + px) * 36];

        // layer0 + leaky + layer1 fused
        float h1[16];
#pragma unroll
        for (int j = 0; j < 16; j++) h1[j] = 0.f;
#pragma unroll
        for (int cg = 0; cg < 8; cg++) {
            float4 hv = Hp[cg];
            float4 pv = Pn4[cg];
            float4 dv = dt4[cg];
            int cb = cg * 4;
            float t, a;
            t = hv.x + pv.x + dv.x; a = fmaxf(t, 0.01f * t);
#pragma unroll
            for (int j = 0; j < 16; j++) h1[j] = fmaf(a, sW1[(cb+0)*16 + j], h1[j]);
            t = hv.y + pv.y + dv.y; a = fmaxf(t, 0.01f * t);
#pragma unroll
            for (int j = 0; j < 16; j++) h1[j] = fmaf(a, sW1[(cb+1)*16 + j], h1[j]);
            t = hv.z + pv.z + dv.z; a = fmaxf(t, 0.01f * t);
#pragma unroll
            for (int j = 0; j < 16; j++) h1[j] = fmaf(a, sW1[(cb+2)*16 + j], h1[j]);
            t = hv.w + pv.w + dv.w; a = fmaxf(t, 0.01f * t);
#pragma unroll
            for (int j = 0; j < 16; j++) h1[j] = fmaf(a, sW1[(cb+3)*16 + j], h1[j]);
        }

        // leaky + layer2 fused
        float h2[8];
#pragma unroll
        for (int j = 0; j < 8; j++) h2[j] = 0.f;
#pragma unroll
        for (int c = 0; c < 16; c++) {
            float a = fmaxf(h1[c], 0.01f * h1[c]);
#pragma unroll
            for (int j = 0; j < 8; j++)
                h2[j] = fmaf(a, sW2[c * 8 + j], h2[j]);
        }

        // leaky + layer3
        float logit = 0.f;
#pragma unroll
        for (int c = 0; c < 8; c++)
            logit = fmaf(fmaxf(h2[c], 0.01f * h2[c]), sW3[c], logit);

        v9[k] = valid ? logit : -100.0f;
    }

    // ---- fused softmax over the 9 logits ----
    float m = v9[0];
#pragma unroll
    for (int k = 1; k < 9; k++) m = fmaxf(m, v9[k]);
    float s = 0.f;
#pragma unroll
    for (int k = 0; k < 9; k++) {
        v9[k] = __expf(v9[k] - m);
        s += v9[k];
    }
    float inv = 1.f / s;

    float* outp = out + ((size_t)b * 9 * H + y) * W + x;
#pragma unroll
    for (int k = 0; k < 9; k++)
        outp[(size_t)k * H * W] = v9[k] * inv;
}

// ---------------------------------------------------------------------------
extern "C" void kernel_launch(void* const* d_in, const int* in_sizes, int n_in,
                              void* d_out, int out_size)
{
    const float* lr = (const float*)d_in[0];
    const float* hr = (const float*)d_in[1];
    // d_in[2], d_in[3] (lr_feature_r / hr_feature_r) are unused by the reference
    const float* w0 = (const float*)d_in[4];
    const float* w1 = (const float*)d_in[5];
    const float* w2 = (const float*)d_in[6];
    const float* w3 = (const float*)d_in[7];
    float* out = (float*)d_out;

    // host-side attribute set (not a stream op; graph-capture safe, idempotent)
    cudaFuncSetAttribute(k_fused, cudaFuncAttributeMaxDynamicSharedMemorySize,
                         SMEM_FLOATS * (int)sizeof(float));

    dim3 grid(W / 64, H / 4, Bn);
    k_fused<<<grid, 256, SMEM_FLOATS * sizeof(float)>>>(lr, hr, w0, w1, w2, w3, out);
}

// round 5
// speedup vs baseline: 5.2879x; 5.2879x over previous
#include <cuda_runtime.h>
#include <math.h>

#define Bn 2
#define C 32
#define H 256
#define W 512
#define LH 64
#define LW 128

// Precomputed lr projection: P[b][ly][lx][o] = W0_lr @ lr   (2 MB scratch)
__device__ float g_P[Bn * LH * LW * 32];

// ---------------------------------------------------------------------------
// Kernel 1: P[b,ly,lx,o] = sum_c w0[o,c] * lr[b,c,ly,lx]
// ---------------------------------------------------------------------------
__global__ __launch_bounds__(256) void k_precompute_P(
    const float* __restrict__ lr, const float* __restrict__ w0)
{
    __shared__ float sw[32 * 32];  // [c][o]
    int t = threadIdx.x;
    for (int i = t; i < 32 * 32; i += 256) {
        int c = i >> 5, o = i & 31;
        sw[i] = w0[o * 66 + c];
    }
    __syncthreads();

    int gid = blockIdx.x * 256 + t;
    int pix = gid >> 2;
    int og  = (gid & 3) * 8;
    if (pix >= Bn * LH * LW) return;
    int b   = pix / (LH * LW);
    int rem = pix - b * (LH * LW);

    const float* lp = lr + (size_t)b * C * LH * LW + rem;
    float acc[8];
#pragma unroll
    for (int o = 0; o < 8; o++) acc[o] = 0.f;
#pragma unroll
    for (int c = 0; c < 32; c++) {
        float v = lp[c * (LH * LW)];
#pragma unroll
        for (int o = 0; o < 8; o++)
            acc[o] = fmaf(v, sw[c * 32 + og + o], acc[o]);
    }
    float* P = g_P + (size_t)pix * 32 + og;
#pragma unroll
    for (int o = 0; o < 8; o++) P[o] = acc[o];
}

// ---------------------------------------------------------------------------
// Main kernel. Block = 64 pixels (one row) x 9 directions = 576 threads.
// warp w (0..17): direction k = w>>1, pixels (w&1)*32 + lane.
// All per-thread state is tiny (h1[16], h2[8]) -> no spills.
// Weight LDS are warp-broadcast (all lanes same address).
// ---------------------------------------------------------------------------
__global__ __launch_bounds__(576, 2) void k_main(
    const float* __restrict__ hr,
    const float* __restrict__ w0,
    const float* __restrict__ w1,
    const float* __restrict__ w2,
    const float* __restrict__ w3,
    float* __restrict__ out)
{
    __shared__ float sW0hr[32 * 32];     // [c][o]
    __shared__ float sW1[32 * 16];       // [c][j]
    __shared__ float sW2[16 * 8];        // [c][j]
    __shared__ float sW3[8];
    __shared__ float sX[32 * 64];        // hr tile [c][pix]
    __shared__ float sHP[64 * 33];       // hpart [pix][o], stride 33
    __shared__ float sP[54 * 33];        // P halo [3 rows x 18 cells][o], stride 33
    __shared__ float sDT[36 * 33];       // dt [k*4+px][o], stride 33 (py fixed)
    __shared__ float sL[9 * 64];         // logits [k][pix]

    const int tid = threadIdx.x;
    const int x0  = blockIdx.x * 64;
    const int y   = blockIdx.y;
    const int b   = blockIdx.z;
    const int py  = y & 3;
    const int ly0 = y >> 2;
    const int lx0 = x0 >> 2;

    // ---- phase 1: stage weights, hr tile, build dt ----
    for (int i = tid; i < 32 * 32; i += 576) {
        int c = i >> 5, o = i & 31;
        sW0hr[i] = w0[o * 66 + 32 + c];
    }
    for (int i = tid; i < 32 * 16; i += 576) {
        int c = i >> 4, j = i & 15;
        sW1[i] = w1[j * 32 + c];
    }
    for (int i = tid; i < 16 * 8; i += 576) {
        int c = i >> 3, j = i & 7;
        sW2[i] = w2[j * 16 + c];
    }
    if (tid < 8) sW3[tid] = w3[tid];

    for (int i = tid; i < 32 * 64; i += 576) {
        int c = i >> 6, p = i & 63;
        sX[i] = hr[(((size_t)b * C + c) * H + y) * W + x0 + p];
    }

    // dt: py is constant for this block -> only [k][px][o]
    {
        float byf = (py < 2) ? (float)(py - 2) : (float)(py - 1);
        for (int i = tid; i < 9 * 4 * 32; i += 576) {
            int o  = i & 31;
            int px = (i >> 5) & 3;
            int k  = i >> 7;
            float bxf = (px < 2) ? (float)(px - 2) : (float)(px - 1);
            float d0, d1;
            if (k == 0)                { d0 = bxf;              d1 = byf;              }
            else if (k == 1 || k == 5) { d0 = 4.f - (float)px;  d1 = byf;              }
            else if (k == 2 || k == 6) { d0 = (float)px + 1.f;  d1 = byf;              }
            else if (k == 3 || k == 7) { d0 = bxf;              d1 = 4.f - (float)py;  }
            else                       { d0 = bxf;              d1 = (float)py + 1.f;  }
            sDT[(k * 4 + px) * 33 + o] =
                w0[o * 66 + 64] * d0 + w0[o * 66 + 65] * d1;
        }
    }
    __syncthreads();

    // ---- phase 2: hpart from sX; P halo from g_P ----
    if (tid < 512) {
        int pix = tid >> 3;
        int og  = (tid & 7) << 2;
        float a0 = 0.f, a1 = 0.f, a2 = 0.f, a3 = 0.f;
#pragma unroll 8
        for (int c = 0; c < 32; c++) {
            float v = sX[c * 64 + pix];
            const float4 wv = *(const float4*)&sW0hr[c * 32 + og];
            a0 = fmaf(v, wv.x, a0);
            a1 = fmaf(v, wv.y, a1);
            a2 = fmaf(v, wv.z, a2);
            a3 = fmaf(v, wv.w, a3);
        }
        float* d = &sHP[pix * 33 + og];
        d[0] = a0; d[1] = a1; d[2] = a2; d[3] = a3;
    }
    for (int i = tid; i < 54 * 32; i += 576) {
        int o    = i & 31;
        int cell = i >> 5;            // 0..53
        int lxl  = cell % 18, lyl = cell / 18;
        int glx  = min(max(lx0 - 1 + lxl, 0), LW - 1);
        int gly  = min(max(ly0 - 1 + lyl, 0), LH - 1);
        sP[cell * 33 + o] = g_P[(((size_t)b * LH + gly) * LW + glx) * 32 + o];
    }
    __syncthreads();

    // ---- phase 3: one direction per thread through the MLP ----
    {
        const int w    = tid >> 5;          // 0..17
        const int k    = w >> 1;            // 0..8
        const int lane = tid & 31;
        const int pix  = ((w & 1) << 5) + lane;   // 0..63
        const int x    = x0 + pix;
        const int px   = x & 3;

        // dir offsets: dy=-1 k in {3,5,6}, dy=+1 {4,7,8}; dx=-1 {1,5,7}, dx=+1 {2,6,8}
        const unsigned NY = (1u<<3)|(1u<<5)|(1u<<6), PY = (1u<<4)|(1u<<7)|(1u<<8);
        const unsigned NX = (1u<<1)|(1u<<5)|(1u<<7), PX = (1u<<2)|(1u<<6)|(1u<<8);
        int dy = (int)((PY >> k) & 1u) - (int)((NY >> k) & 1u);
        int dx = (int)((PX >> k) & 1u) - (int)((NX >> k) & 1u);
        int xn = x + dx * 4, yn = y + dy * 4;
        bool valid = (xn >= 0) & (xn < W) & (yn >= 0) & (yn < H);

        int cell = (1 + dy) * 18 + (pix >> 2) + 1 + dx;
        const float* hpr = &sHP[pix * 33];
        const float* pr  = &sP[cell * 33];
        const float* dtr = &sDT[(k * 4 + px) * 33];

        float h1[16];
#pragma unroll
        for (int j = 0; j < 16; j++) h1[j] = 0.f;

#pragma unroll 4
        for (int c = 0; c < 32; c++) {
            float t = hpr[c] + pr[c] + dtr[c];
            float a = fmaxf(t, 0.01f * t);
            const float4 w1a = *(const float4*)&sW1[c * 16];
            const float4 w1b = *(const float4*)&sW1[c * 16 + 4];
            const float4 w1c = *(const float4*)&sW1[c * 16 + 8];
            const float4 w1d = *(const float4*)&sW1[c * 16 + 12];
            h1[0]  = fmaf(a, w1a.x, h1[0]);  h1[1]  = fmaf(a, w1a.y, h1[1]);
            h1[2]  = fmaf(a, w1a.z, h1[2]);  h1[3]  = fmaf(a, w1a.w, h1[3]);
            h1[4]  = fmaf(a, w1b.x, h1[4]);  h1[5]  = fmaf(a, w1b.y, h1[5]);
            h1[6]  = fmaf(a, w1b.z, h1[6]);  h1[7]  = fmaf(a, w1b.w, h1[7]);
            h1[8]  = fmaf(a, w1c.x, h1[8]);  h1[9]  = fmaf(a, w1c.y, h1[9]);
            h1[10] = fmaf(a, w1c.z, h1[10]); h1[11] = fmaf(a, w1c.w, h1[11]);
            h1[12] = fmaf(a, w1d.x, h1[12]); h1[13] = fmaf(a, w1d.y, h1[13]);
            h1[14] = fmaf(a, w1d.z, h1[14]); h1[15] = fmaf(a, w1d.w, h1[15]);
        }

        float h2[8];
#pragma unroll
        for (int j = 0; j < 8; j++) h2[j] = 0.f;
#pragma unroll 4
        for (int c = 0; c < 16; c++) {
            float a = fmaxf(h1[c], 0.01f * h1[c]);
            const float4 w2a = *(const float4*)&sW2[c * 8];
            const float4 w2b = *(const float4*)&sW2[c * 8 + 4];
            h2[0] = fmaf(a, w2a.x, h2[0]); h2[1] = fmaf(a, w2a.y, h2[1]);
            h2[2] = fmaf(a, w2a.z, h2[2]); h2[3] = fmaf(a, w2a.w, h2[3]);
            h2[4] = fmaf(a, w2b.x, h2[4]); h2[5] = fmaf(a, w2b.y, h2[5]);
            h2[6] = fmaf(a, w2b.z, h2[6]); h2[7] = fmaf(a, w2b.w, h2[7]);
        }

        float logit = 0.f;
#pragma unroll
        for (int c = 0; c < 8; c++)
            logit = fmaf(fmaxf(h2[c], 0.01f * h2[c]), sW3[c], logit);

        sL[k * 64 + pix] = valid ? logit : -100.0f;
    }
    __syncthreads();

    // ---- phase 4: softmax over 9 dirs, write out ----
    if (tid < 64) {
        float v[9], m = -1e30f;
#pragma unroll
        for (int k = 0; k < 9; k++) {
            v[k] = sL[k * 64 + tid];
            m = fmaxf(m, v[k]);
        }
        float s = 0.f;
#pragma unroll
        for (int k = 0; k < 9; k++) {
            v[k] = __expf(v[k] - m);
            s += v[k];
        }
        float inv = 1.f / s;
        float* op = out + (((size_t)b * 9) * H + y) * W + x0 + tid;
#pragma unroll
        for (int k = 0; k < 9; k++)
            op[(size_t)k * H * W] = v[k] * inv;
    }
}

// ---------------------------------------------------------------------------
extern "C" void kernel_launch(void* const* d_in, const int* in_sizes, int n_in,
                              void* d_out, int out_size)
{
    const float* lr = (const float*)d_in[0];
    const float* hr = (const float*)d_in[1];
    // d_in[2], d_in[3] (lr_feature_r / hr_feature_r) unused by the reference
    const float* w0 = (const float*)d_in[4];
    const float* w1 = (const float*)d_in[5];
    const float* w2 = (const float*)d_in[6];
    const float* w3 = (const float*)d_in[7];
    float* out = (float*)d_out;

    k_precompute_P<<<(Bn * LH * LW * 4 + 255) / 256, 256>>>(lr, w0);

    dim3 grid(W / 64, H, Bn);
    k_main<<<grid, 576>>>(hr, w0, w1, w2, w3, out);
}

// round 6
// speedup vs baseline: 5.7518x; 1.0877x over previous
#include <cuda_runtime.h>
#include <math.h>

#define Bn 2
#define C 32
#define H 256
#define W 512
#define LH 64
#define LW 128

// Precomputed lr projection: P[b][ly][lx][o] = W0_lr @ lr   (2 MB scratch)
__device__ float g_P[Bn * LH * LW * 32];

// ---------------------------------------------------------------------------
// Kernel 1: P[b,ly,lx,o] = sum_c w0[o,c] * lr[b,c,ly,lx]
// ---------------------------------------------------------------------------
__global__ __launch_bounds__(256) void k_precompute_P(
    const float* __restrict__ lr, const float* __restrict__ w0)
{
    __shared__ float sw[32 * 32];  // [c][o]
    int t = threadIdx.x;
    for (int i = t; i < 32 * 32; i += 256) {
        int c = i >> 5, o = i & 31;
        sw[i] = w0[o * 66 + c];
    }
    __syncthreads();

    int gid = blockIdx.x * 256 + t;
    int pix = gid >> 2;
    int og  = (gid & 3) * 8;
    if (pix >= Bn * LH * LW) return;
    int b   = pix / (LH * LW);
    int rem = pix - b * (LH * LW);

    const float* lp = lr + (size_t)b * C * LH * LW + rem;
    float acc[8];
#pragma unroll
    for (int o = 0; o < 8; o++) acc[o] = 0.f;
#pragma unroll
    for (int c = 0; c < 32; c++) {
        float v = lp[c * (LH * LW)];
#pragma unroll
        for (int o = 0; o < 8; o++)
            acc[o] = fmaf(v, sw[c * 32 + og + o], acc[o]);
    }
    float* P = g_P + (size_t)pix * 32 + og;
#pragma unroll
    for (int o = 0; o < 8; o++) P[o] = acc[o];
}

// ---------------------------------------------------------------------------
// Main kernel. Block = 64-pixel strip (one row) x 9 directions.
// 288 threads = 9 warps; warp k owns direction k; lane handles pixels
// lane and lane+32 (same 4-phase px, so dt row is shared).
// ---------------------------------------------------------------------------
__global__ __launch_bounds__(288, 3) void k_main(
    const float* __restrict__ hr,
    const float* __restrict__ w0,
    const float* __restrict__ w1,
    const float* __restrict__ w2,
    const float* __restrict__ w3,
    float* __restrict__ out)
{
    __shared__ float sW0hr[32 * 32];     // [c][o]
    __shared__ float sW1[32 * 16];       // [c][j]
    __shared__ float sW2[16 * 8];        // [c][j]
    __shared__ float sW3[8];
    __shared__ float sX[32 * 64];        // hr tile [c][pix]
    __shared__ float sHP[64 * 33];       // hpart [pix][o], stride 33 (16B-aligned rows? 33*4=132 -> need aligned float4: use offset c multiples of 4 within row; row base 33*pix*4B not 16B aligned!)
    __shared__ float sP[54 * 33];
    __shared__ float sDT[36 * 33];
    __shared__ float sL[9 * 64];

    const int tid = threadIdx.x;
    const int x0  = blockIdx.x * 64;
    const int y   = blockIdx.y;
    const int b   = blockIdx.z;
    const int py  = y & 3;
    const int ly0 = y >> 2;
    const int lx0 = x0 >> 2;

    // ---- phase 1: stage weights, hr tile, build dt ----
    for (int i = tid; i < 32 * 32; i += 288) {
        int c = i >> 5, o = i & 31;
        sW0hr[i] = w0[o * 66 + 32 + c];
    }
    for (int i = tid; i < 32 * 16; i += 288) {
        int c = i >> 4, j = i & 15;
        sW1[i] = w1[j * 32 + c];
    }
    for (int i = tid; i < 16 * 8; i += 288) {
        int c = i >> 3, j = i & 7;
        sW2[i] = w2[j * 16 + c];
    }
    if (tid < 8) sW3[tid] = w3[tid];

    for (int i = tid; i < 32 * 64; i += 288) {
        int c = i >> 6, p = i & 63;
        sX[i] = hr[(((size_t)b * C + c) * H + y) * W + x0 + p];
    }

    {
        float byf = (py < 2) ? (float)(py - 2) : (float)(py - 1);
        for (int i = tid; i < 9 * 4 * 32; i += 288) {
            int o  = i & 31;
            int px = (i >> 5) & 3;
            int k  = i >> 7;
            float bxf = (px < 2) ? (float)(px - 2) : (float)(px - 1);
            float d0, d1;
            if (k == 0)                { d0 = bxf;              d1 = byf;              }
            else if (k == 1 || k == 5) { d0 = 4.f - (float)px;  d1 = byf;              }
            else if (k == 2 || k == 6) { d0 = (float)px + 1.f;  d1 = byf;              }
            else if (k == 3 || k == 7) { d0 = bxf;              d1 = 4.f - (float)py;  }
            else                       { d0 = bxf;              d1 = (float)py + 1.f;  }
            sDT[(k * 4 + px) * 33 + o] =
                w0[o * 66 + 64] * d0 + w0[o * 66 + 65] * d1;
        }
    }
    __syncthreads();

    // ---- phase 2: hpart from sX; P halo from g_P ----
    for (int i = tid; i < 512; i += 288) {
        int pix = i >> 3;
        int og  = (i & 7) << 2;
        float a0 = 0.f, a1 = 0.f, a2 = 0.f, a3 = 0.f;
#pragma unroll 8
        for (int c = 0; c < 32; c++) {
            float v = sX[c * 64 + pix];
            const float4 wv = *(const float4*)&sW0hr[c * 32 + og];
            a0 = fmaf(v, wv.x, a0);
            a1 = fmaf(v, wv.y, a1);
            a2 = fmaf(v, wv.z, a2);
            a3 = fmaf(v, wv.w, a3);
        }
        float* d = &sHP[pix * 33 + og];
        d[0] = a0; d[1] = a1; d[2] = a2; d[3] = a3;
    }
    for (int i = tid; i < 54 * 32; i += 288) {
        int o    = i & 31;
        int cell = i >> 5;
        int lxl  = cell % 18, lyl = cell / 18;
        int glx  = min(max(lx0 - 1 + lxl, 0), LW - 1);
        int gly  = min(max(ly0 - 1 + lyl, 0), LH - 1);
        sP[cell * 33 + o] = g_P[(((size_t)b * LH + gly) * LW + glx) * 32 + o];
    }
    __syncthreads();

    // ---- phase 3: warp k = direction k; lane does pixels lane, lane+32 ----
    {
        const int k    = tid >> 5;          // 0..8
        const int lane = tid & 31;
        const int pA   = lane;              // pixel A
        const int pB   = lane + 32;         // pixel B (same px phase)
        const int px   = pA & 3;

        // dir offsets: dy=-1 k in {3,5,6}, dy=+1 {4,7,8}; dx=-1 {1,5,7}, dx=+1 {2,6,8}
        const unsigned NY = (1u<<3)|(1u<<5)|(1u<<6), PY = (1u<<4)|(1u<<7)|(1u<<8);
        const unsigned NX = (1u<<1)|(1u<<5)|(1u<<7), PX = (1u<<2)|(1u<<6)|(1u<<8);
        int dy = (int)((PY >> k) & 1u) - (int)((NY >> k) & 1u);
        int dx = (int)((PX >> k) & 1u) - (int)((NX >> k) & 1u);
        int yn = y + dy * 4;
        bool vy = (yn >= 0) & (yn < H);
        int xnA = x0 + pA + dx * 4;
        int xnB = x0 + pB + dx * 4;
        bool validA = vy & (xnA >= 0) & (xnA < W);
        bool validB = vy & (xnB >= 0) & (xnB < W);

        const float* hpA = &sHP[pA * 33];
        const float* hpB = &sHP[pB * 33];
        const float* prA = &sP[((1 + dy) * 18 + (pA >> 2) + 1 + dx) * 33];
        const float* prB = prA + 8 * 33;          // (pB>>2) = (pA>>2) + 8
        const float* dtr = &sDT[(k * 4 + px) * 33];

        float h1a[16], h1b[16];
#pragma unroll
        for (int j = 0; j < 16; j++) { h1a[j] = 0.f; h1b[j] = 0.f; }

#pragma unroll 2
        for (int c4 = 0; c4 < 32; c4 += 4) {
            // rows have odd stride 33 -> float4 via element loads only where
            // base not 16B aligned; sHP/sP/sDT rows are 4B aligned. Use
            // scalar loads for acts (compiler may vectorize the dt row).
            float aA[4], aB[4];
#pragma unroll
            for (int cc = 0; cc < 4; cc++) {
                float dtv = dtr[c4 + cc];
                float tA = hpA[c4 + cc] + prA[c4 + cc] + dtv;
                float tB = hpB[c4 + cc] + prB[c4 + cc] + dtv;
                aA[cc] = fmaxf(tA, 0.01f * tA);
                aB[cc] = fmaxf(tB, 0.01f * tB);
            }
#pragma unroll
            for (int cc = 0; cc < 4; cc++) {
                const int c = c4 + cc;
                const float4 w1a = *(const float4*)&sW1[c * 16];
                const float4 w1b = *(const float4*)&sW1[c * 16 + 4];
                const float4 w1c = *(const float4*)&sW1[c * 16 + 8];
                const float4 w1d = *(const float4*)&sW1[c * 16 + 12];
                float vA = aA[cc], vB = aB[cc];
                h1a[0]  = fmaf(vA, w1a.x, h1a[0]);  h1b[0]  = fmaf(vB, w1a.x, h1b[0]);
                h1a[1]  = fmaf(vA, w1a.y, h1a[1]);  h1b[1]  = fmaf(vB, w1a.y, h1b[1]);
                h1a[2]  = fmaf(vA, w1a.z, h1a[2]);  h1b[2]  = fmaf(vB, w1a.z, h1b[2]);
                h1a[3]  = fmaf(vA, w1a.w, h1a[3]);  h1b[3]  = fmaf(vB, w1a.w, h1b[3]);
                h1a[4]  = fmaf(vA, w1b.x, h1a[4]);  h1b[4]  = fmaf(vB, w1b.x, h1b[4]);
                h1a[5]  = fmaf(vA, w1b.y, h1a[5]);  h1b[5]  = fmaf(vB, w1b.y, h1b[5]);
                h1a[6]  = fmaf(vA, w1b.z, h1a[6]);  h1b[6]  = fmaf(vB, w1b.z, h1b[6]);
                h1a[7]  = fmaf(vA, w1b.w, h1a[7]);  h1b[7]  = fmaf(vB, w1b.w, h1b[7]);
                h1a[8]  = fmaf(vA, w1c.x, h1a[8]);  h1b[8]  = fmaf(vB, w1c.x, h1b[8]);
                h1a[9]  = fmaf(vA, w1c.y, h1a[9]);  h1b[9]  = fmaf(vB, w1c.y, h1b[9]);
                h1a[10] = fmaf(vA, w1c.z, h1a[10]); h1b[10] = fmaf(vB, w1c.z, h1b[10]);
                h1a[11] = fmaf(vA, w1c.w, h1a[11]); h1b[11] = fmaf(vB, w1c.w, h1b[11]);
                h1a[12] = fmaf(vA, w1d.x, h1a[12]); h1b[12] = fmaf(vB, w1d.x, h1b[12]);
                h1a[13] = fmaf(vA, w1d.y, h1a[13]); h1b[13] = fmaf(vB, w1d.y, h1b[13]);
                h1a[14] = fmaf(vA, w1d.z, h1a[14]); h1b[14] = fmaf(vB, w1d.z, h1b[14]);
                h1a[15] = fmaf(vA, w1d.w, h1a[15]); h1b[15] = fmaf(vB, w1d.w, h1b[15]);
            }
        }

        float h2a[8], h2b[8];
#pragma unroll
        for (int j = 0; j < 8; j++) { h2a[j] = 0.f; h2b[j] = 0.f; }
#pragma unroll 4
        for (int c = 0; c < 16; c++) {
            float vA = fmaxf(h1a[c], 0.01f * h1a[c]);
            float vB = fmaxf(h1b[c], 0.01f * h1b[c]);
            const float4 w2a = *(const float4*)&sW2[c * 8];
            const float4 w2b = *(const float4*)&sW2[c * 8 + 4];
            h2a[0] = fmaf(vA, w2a.x, h2a[0]); h2b[0] = fmaf(vB, w2a.x, h2b[0]);
            h2a[1] = fmaf(vA, w2a.y, h2a[1]); h2b[1] = fmaf(vB, w2a.y, h2b[1]);
            h2a[2] = fmaf(vA, w2a.z, h2a[2]); h2b[2] = fmaf(vB, w2a.z, h2b[2]);
            h2a[3] = fmaf(vA, w2a.w, h2a[3]); h2b[3] = fmaf(vB, w2a.w, h2b[3]);
            h2a[4] = fmaf(vA, w2b.x, h2a[4]); h2b[4] = fmaf(vB, w2b.x, h2b[4]);
            h2a[5] = fmaf(vA, w2b.y, h2a[5]); h2b[5] = fmaf(vB, w2b.y, h2b[5]);
            h2a[6] = fmaf(vA, w2b.z, h2a[6]); h2b[6] = fmaf(vB, w2b.z, h2b[6]);
            h2a[7] = fmaf(vA, w2b.w, h2a[7]); h2b[7] = fmaf(vB, w2b.w, h2b[7]);
        }

        float logitA = 0.f, logitB = 0.f;
#pragma unroll
        for (int c = 0; c < 8; c++) {
            float wv = sW3[c];
            logitA = fmaf(fmaxf(h2a[c], 0.01f * h2a[c]), wv, logitA);
            logitB = fmaf(fmaxf(h2b[c], 0.01f * h2b[c]), wv, logitB);
        }

        sL[k * 64 + pA] = validA ? logitA : -100.0f;
        sL[k * 64 + pB] = validB ? logitB : -100.0f;
    }
    __syncthreads();

    // ---- phase 4: softmax over 9 dirs, write out ----
    if (tid < 64) {
        float v[9], m = -1e30f;
#pragma unroll
        for (int k = 0; k < 9; k++) {
            v[k] = sL[k * 64 + tid];
            m = fmaxf(m, v[k]);
        }
        float s = 0.f;
#pragma unroll
        for (int k = 0; k < 9; k++) {
            v[k] = __expf(v[k] - m);
            s += v[k];
        }
        float inv = 1.f / s;
        float* op = out + (((size_t)b * 9) * H + y) * W + x0 + tid;
#pragma unroll
        for (int k = 0; k < 9; k++)
            op[(size_t)k * H * W] = v[k] * inv;
    }
}

// ---------------------------------------------------------------------------
extern "C" void kernel_launch(void* const* d_in, const int* in_sizes, int n_in,
                              void* d_out, int out_size)
{
    const float* lr = (const float*)d_in[0];
    const float* hr = (const float*)d_in[1];
    // d_in[2], d_in[3] (lr_feature_r / hr_feature_r) unused by the reference
    const float* w0 = (const float*)d_in[4];
    const float* w1 = (const float*)d_in[5];
    const float* w2 = (const float*)d_in[6];
    const float* w3 = (const float*)d_in[7];
    float* out = (float*)d_out;

    k_precompute_P<<<(Bn * LH * LW * 4 + 255) / 256, 256>>>(lr, w0);

    dim3 grid(W / 64, H, Bn);
    k_main<<<grid, 288>>>(hr, w0, w1, w2, w3, out);
}

// round 7
// speedup vs baseline: 6.4775x; 1.1262x over previous
#include <cuda_runtime.h>
#include <math.h>

#define Bn 2
#define C 32
#define H 256
#define W 512
#define LH 64
#define LW 128

#define STR 36   // row stride (floats): 144B = 16B-aligned rows, bank-rotates by 4

// Precomputed lr projection: P[b][ly][lx][o] = W0_lr @ lr   (2 MB scratch)
__device__ float g_P[Bn * LH * LW * 32];

// ---------------------------------------------------------------------------
// Kernel 1: P[b,ly,lx,o] = sum_c w0[o,c] * lr[b,c,ly,lx]
// ---------------------------------------------------------------------------
__global__ __launch_bounds__(256) void k_precompute_P(
    const float* __restrict__ lr, const float* __restrict__ w0)
{
    __shared__ float sw[32 * 32];  // [c][o]
    int t = threadIdx.x;
    for (int i = t; i < 32 * 32; i += 256) {
        int c = i >> 5, o = i & 31;
        sw[i] = w0[o * 66 + c];
    }
    __syncthreads();

    int gid = blockIdx.x * 256 + t;
    int pix = gid >> 2;
    int og  = (gid & 3) * 8;
    if (pix >= Bn * LH * LW) return;
    int b   = pix / (LH * LW);
    int rem = pix - b * (LH * LW);

    const float* lp = lr + (size_t)b * C * LH * LW + rem;
    float acc[8];
#pragma unroll
    for (int o = 0; o < 8; o++) acc[o] = 0.f;
#pragma unroll
    for (int c = 0; c < 32; c++) {
        float v = lp[c * (LH * LW)];
#pragma unroll
        for (int o = 0; o < 8; o++)
            acc[o] = fmaf(v, sw[c * 32 + og + o], acc[o]);
    }
    float* P = g_P + (size_t)pix * 32 + og;
#pragma unroll
    for (int o = 0; o < 8; o++) P[o] = acc[o];
}

// ---------------------------------------------------------------------------
// Main kernel. Block = 64-pixel strip (one row) x 9 directions.
// 288 threads = 9 warps; warp k owns direction k; lane handles pixels
// lane and lane+32 (same 4-phase px, so dt row is shared).
// All activation tables are stride-36 so float4 LDS are aligned + conflict-free.
// ---------------------------------------------------------------------------
__global__ __launch_bounds__(288, 3) void k_main(
    const float* __restrict__ hr,
    const float* __restrict__ w0,
    const float* __restrict__ w1,
    const float* __restrict__ w2,
    const float* __restrict__ w3,
    float* __restrict__ out)
{
    __shared__ float sW0hr[32 * 32];     // [c][o]
    __shared__ float sW1[32 * 16];       // [c][j]
    __shared__ float sW2[16 * 8];        // [c][j]
    __shared__ float sW3[8];
    __shared__ float sX[32 * 64];        // hr tile [c][pix]
    __shared__ float sHP[64 * STR];      // hpart [pix][o]
    __shared__ float sP[54 * STR];       // P halo [3x18 cells][o]
    __shared__ float sDT[36 * STR];      // dt [k*4+px][o]
    __shared__ float sL[9 * 64];         // logits [k][pix]

    const int tid = threadIdx.x;
    const int x0  = blockIdx.x * 64;
    const int y   = blockIdx.y;
    const int b   = blockIdx.z;
    const int py  = y & 3;
    const int ly0 = y >> 2;
    const int lx0 = x0 >> 2;

    // ---- phase 1: stage weights, hr tile, build dt ----
    for (int i = tid; i < 32 * 32; i += 288) {
        int c = i >> 5, o = i & 31;
        sW0hr[i] = w0[o * 66 + 32 + c];
    }
    for (int i = tid; i < 32 * 16; i += 288) {
        int c = i >> 4, j = i & 15;
        sW1[i] = w1[j * 32 + c];
    }
    for (int i = tid; i < 16 * 8; i += 288) {
        int c = i >> 3, j = i & 7;
        sW2[i] = w2[j * 16 + c];
    }
    if (tid < 8) sW3[tid] = w3[tid];

    for (int i = tid; i < 32 * 64; i += 288) {
        int c = i >> 6, p = i & 63;
        sX[i] = hr[(((size_t)b * C + c) * H + y) * W + x0 + p];
    }

    {
        float byf = (py < 2) ? (float)(py - 2) : (float)(py - 1);
        for (int i = tid; i < 9 * 4 * 32; i += 288) {
            int o  = i & 31;
            int px = (i >> 5) & 3;
            int k  = i >> 7;
            float bxf = (px < 2) ? (float)(px - 2) : (float)(px - 1);
            float d0, d1;
            if (k == 0)                { d0 = bxf;              d1 = byf;              }
            else if (k == 1 || k == 5) { d0 = 4.f - (float)px;  d1 = byf;              }
            else if (k == 2 || k == 6) { d0 = (float)px + 1.f;  d1 = byf;              }
            else if (k == 3 || k == 7) { d0 = bxf;              d1 = 4.f - (float)py;  }
            else                       { d0 = bxf;              d1 = (float)py + 1.f;  }
            sDT[(k * 4 + px) * STR + o] =
                w0[o * 66 + 64] * d0 + w0[o * 66 + 65] * d1;
        }
    }
    __syncthreads();

    // ---- phase 2: hpart from sX; P halo from g_P (float4 copies) ----
    for (int i = tid; i < 512; i += 288) {
        int pix = i >> 3;
        int og  = (i & 7) << 2;
        float a0 = 0.f, a1 = 0.f, a2 = 0.f, a3 = 0.f;
#pragma unroll 8
        for (int c = 0; c < 32; c++) {
            float v = sX[c * 64 + pix];
            const float4 wv = *(const float4*)&sW0hr[c * 32 + og];
            a0 = fmaf(v, wv.x, a0);
            a1 = fmaf(v, wv.y, a1);
            a2 = fmaf(v, wv.z, a2);
            a3 = fmaf(v, wv.w, a3);
        }
        *(float4*)&sHP[pix * STR + og] = make_float4(a0, a1, a2, a3);
    }
    for (int i = tid; i < 54 * 8; i += 288) {
        int cell = i >> 3;
        int og   = (i & 7) << 2;
        int lxl  = cell % 18, lyl = cell / 18;
        int glx  = min(max(lx0 - 1 + lxl, 0), LW - 1);
        int gly  = min(max(ly0 - 1 + lyl, 0), LH - 1);
        float4 v = *(const float4*)&g_P[(((size_t)b * LH + gly) * LW + glx) * 32 + og];
        *(float4*)&sP[cell * STR + og] = v;
    }
    __syncthreads();

    // ---- phase 3: warp k = direction k; lane does pixels lane, lane+32 ----
    {
        const int k    = tid >> 5;          // 0..8
        const int lane = tid & 31;
        const int pA   = lane;
        const int pB   = lane + 32;
        const int px   = pA & 3;

        // dir offsets: dy=-1 k in {3,5,6}, dy=+1 {4,7,8}; dx=-1 {1,5,7}, dx=+1 {2,6,8}
        const unsigned NY = (1u<<3)|(1u<<5)|(1u<<6), PY = (1u<<4)|(1u<<7)|(1u<<8);
        const unsigned NX = (1u<<1)|(1u<<5)|(1u<<7), PX = (1u<<2)|(1u<<6)|(1u<<8);
        int dy = (int)((PY >> k) & 1u) - (int)((NY >> k) & 1u);
        int dx = (int)((PX >> k) & 1u) - (int)((NX >> k) & 1u);
        int yn = y + dy * 4;
        bool vy = (yn >= 0) & (yn < H);
        int xnA = x0 + pA + dx * 4;
        int xnB = x0 + pB + dx * 4;
        bool validA = vy & (xnA >= 0) & (xnA < W);
        bool validB = vy & (xnB >= 0) & (xnB < W);

        const float* hpA = &sHP[pA * STR];
        const float* hpB = &sHP[pB * STR];
        const float* prA = &sP[((1 + dy) * 18 + (pA >> 2) + 1 + dx) * STR];
        const float* prB = prA + 8 * STR;
        const float* dtr = &sDT[(k * 4 + px) * STR];

        float h1a[16], h1b[16];
#pragma unroll
        for (int j = 0; j < 16; j++) { h1a[j] = 0.f; h1b[j] = 0.f; }

#pragma unroll 2
        for (int c4 = 0; c4 < 32; c4 += 4) {
            const float4 hA4 = *(const float4*)&hpA[c4];
            const float4 hB4 = *(const float4*)&hpB[c4];
            const float4 pA4 = *(const float4*)&prA[c4];
            const float4 pB4 = *(const float4*)&prB[c4];
            const float4 dt4 = *(const float4*)&dtr[c4];

            float aA[4], aB[4];
            {
                float t;
                t = hA4.x + pA4.x + dt4.x; aA[0] = fmaxf(t, 0.01f * t);
                t = hA4.y + pA4.y + dt4.y; aA[1] = fmaxf(t, 0.01f * t);
                t = hA4.z + pA4.z + dt4.z; aA[2] = fmaxf(t, 0.01f * t);
                t = hA4.w + pA4.w + dt4.w; aA[3] = fmaxf(t, 0.01f * t);
                t = hB4.x + pB4.x + dt4.x; aB[0] = fmaxf(t, 0.01f * t);
                t = hB4.y + pB4.y + dt4.y; aB[1] = fmaxf(t, 0.01f * t);
                t = hB4.z + pB4.z + dt4.z; aB[2] = fmaxf(t, 0.01f * t);
                t = hB4.w + pB4.w + dt4.w; aB[3] = fmaxf(t, 0.01f * t);
            }
#pragma unroll
            for (int cc = 0; cc < 4; cc++) {
                const int c = c4 + cc;
                const float4 w1a = *(const float4*)&sW1[c * 16];
                const float4 w1b = *(const float4*)&sW1[c * 16 + 4];
                const float4 w1c = *(const float4*)&sW1[c * 16 + 8];
                const float4 w1d = *(const float4*)&sW1[c * 16 + 12];
                float vA = aA[cc], vB = aB[cc];
                h1a[0]  = fmaf(vA, w1a.x, h1a[0]);  h1b[0]  = fmaf(vB, w1a.x, h1b[0]);
                h1a[1]  = fmaf(vA, w1a.y, h1a[1]);  h1b[1]  = fmaf(vB, w1a.y, h1b[1]);
                h1a[2]  = fmaf(vA, w1a.z, h1a[2]);  h1b[2]  = fmaf(vB, w1a.z, h1b[2]);
                h1a[3]  = fmaf(vA, w1a.w, h1a[3]);  h1b[3]  = fmaf(vB, w1a.w, h1b[3]);
                h1a[4]  = fmaf(vA, w1b.x, h1a[4]);  h1b[4]  = fmaf(vB, w1b.x, h1b[4]);
                h1a[5]  = fmaf(vA, w1b.y, h1a[5]);  h1b[5]  = fmaf(vB, w1b.y, h1b[5]);
                h1a[6]  = fmaf(vA, w1b.z, h1a[6]);  h1b[6]  = fmaf(vB, w1b.z, h1b[6]);
                h1a[7]  = fmaf(vA, w1b.w, h1a[7]);  h1b[7]  = fmaf(vB, w1b.w, h1b[7]);
                h1a[8]  = fmaf(vA, w1c.x, h1a[8]);  h1b[8]  = fmaf(vB, w1c.x, h1b[8]);
                h1a[9]  = fmaf(vA, w1c.y, h1a[9]);  h1b[9]  = fmaf(vB, w1c.y, h1b[9]);
                h1a[10] = fmaf(vA, w1c.z, h1a[10]); h1b[10] = fmaf(vB, w1c.z, h1b[10]);
                h1a[11] = fmaf(vA, w1c.w, h1a[11]); h1b[11] = fmaf(vB, w1c.w, h1b[11]);
                h1a[12] = fmaf(vA, w1d.x, h1a[12]); h1b[12] = fmaf(vB, w1d.x, h1b[12]);
                h1a[13] = fmaf(vA, w1d.y, h1a[13]); h1b[13] = fmaf(vB, w1d.y, h1b[13]);
                h1a[14] = fmaf(vA, w1d.z, h1a[14]); h1b[14] = fmaf(vB, w1d.z, h1b[14]);
                h1a[15] = fmaf(vA, w1d.w, h1a[15]); h1b[15] = fmaf(vB, w1d.w, h1b[15]);
            }
        }

        float h2a[8], h2b[8];
#pragma unroll
        for (int j = 0; j < 8; j++) { h2a[j] = 0.f; h2b[j] = 0.f; }
#pragma unroll 4
        for (int c = 0; c < 16; c++) {
            float vA = fmaxf(h1a[c], 0.01f * h1a[c]);
            float vB = fmaxf(h1b[c], 0.01f * h1b[c]);
            const float4 w2a = *(const float4*)&sW2[c * 8];
            const float4 w2b = *(const float4*)&sW2[c * 8 + 4];
            h2a[0] = fmaf(vA, w2a.x, h2a[0]); h2b[0] = fmaf(vB, w2a.x, h2b[0]);
            h2a[1] = fmaf(vA, w2a.y, h2a[1]); h2b[1] = fmaf(vB, w2a.y, h2b[1]);
            h2a[2] = fmaf(vA, w2a.z, h2a[2]); h2b[2] = fmaf(vB, w2a.z, h2b[2]);
            h2a[3] = fmaf(vA, w2a.w, h2a[3]); h2b[3] = fmaf(vB, w2a.w, h2b[3]);
            h2a[4] = fmaf(vA, w2b.x, h2a[4]); h2b[4] = fmaf(vB, w2b.x, h2b[4]);
            h2a[5] = fmaf(vA, w2b.y, h2a[5]); h2b[5] = fmaf(vB, w2b.y, h2b[5]);
            h2a[6] = fmaf(vA, w2b.z, h2a[6]); h2b[6] = fmaf(vB, w2b.z, h2b[6]);
            h2a[7] = fmaf(vA, w2b.w, h2a[7]); h2b[7] = fmaf(vB, w2b.w, h2b[7]);
        }

        float logitA = 0.f, logitB = 0.f;
#pragma unroll
        for (int c = 0; c < 8; c++) {
            float wv = sW3[c];
            logitA = fmaf(fmaxf(h2a[c], 0.01f * h2a[c]), wv, logitA);
            logitB = fmaf(fmaxf(h2b[c], 0.01f * h2b[c]), wv, logitB);
        }

        sL[k * 64 + pA] = validA ? logitA : -100.0f;
        sL[k * 64 + pB] = validB ? logitB : -100.0f;
    }
    __syncthreads();

    // ---- phase 4: softmax over 9 dirs, write out ----
    if (tid < 64) {
        float v[9], m = -1e30f;
#pragma unroll
        for (int k = 0; k < 9; k++) {
            v[k] = sL[k * 64 + tid];
            m = fmaxf(m, v[k]);
        }
        float s = 0.f;
#pragma unroll
        for (int k = 0; k < 9; k++) {
            v[k] = __expf(v[k] - m);
            s += v[k];
        }
        float inv = 1.f / s;
        float* op = out + (((size_t)b * 9) * H + y) * W + x0 + tid;
#pragma unroll
        for (int k = 0; k < 9; k++)
            op[(size_t)k * H * W] = v[k] * inv;
    }
}

// ---------------------------------------------------------------------------
extern "C" void kernel_launch(void* const* d_in, const int* in_sizes, int n_in,
                              void* d_out, int out_size)
{
    const float* lr = (const float*)d_in[0];
    const float* hr = (const float*)d_in[1];
    // d_in[2], d_in[3] (lr_feature_r / hr_feature_r) unused by the reference
    const float* w0 = (const float*)d_in[4];
    const float* w1 = (const float*)d_in[5];
    const float* w2 = (const float*)d_in[6];
    const float* w3 = (const float*)d_in[7];
    float* out = (float*)d_out;

    k_precompute_P<<<(Bn * LH * LW * 4 + 255) / 256, 256>>>(lr, w0);

    dim3 grid(W / 64, H, Bn);
    k_main<<<grid, 288>>>(hr, w0, w1, w2, w3, out);
}